// round 3
// baseline (speedup 1.0000x reference)
#include <cuda_runtime.h>
#include <math.h>

// ---------------- problem constants ----------------
#define NPTS   200000
#define DF     128
#define NXC    250
#define NYC    250
#define NZC    20
#define VXYZ   1250000           // NXC*NYC*NZC
#define NVKEY  10000000          // B * VXYZ
#define NAKEY  5000000           // (B/2) * VXYZ
#define VWORDS 312500            // NVKEY/32
#define AWORDS 156250            // NAKEY/32
#define VBLOCKS 1221             // ceil(VWORDS/256)
#define ABLOCKS 611              // ceil(AWORDS/256)
#define GEMM_BLOCKS 3125         // NPTS/64

// ---------------- device scratch (no allocs allowed) ----------------
__device__ unsigned g_bitV[VWORDS];
__device__ unsigned g_bitA[AWORDS];
__device__ int g_prefV[VWORDS];
__device__ int g_prefA[AWORDS];
__device__ int g_blkV[VBLOCKS];
__device__ int g_blkA[ABLOCKS];
__device__ int g_vkey[NPTS];
__device__ int g_akey[NPTS];
__device__ int g_inv[NPTS];
__device__ int g_arank[NPTS];
__device__ int g_clusterA[NPTS];
__device__ float g_cnt[NPTS];
__device__ float g_acnt[NPTS];
__device__ float4 g_csum4[NPTS * DF / 4];   // cluster feature sums (then means)
__device__ float4 g_asum4[NPTS * DF / 4];   // associate sums of cfa
__device__ float4 g_cfa4[NPTS * DF / 4];    // projected cluster features
__device__ int g_K;            // max foreground inv (K = g_K+1)
__device__ int g_amaskCnt;
__device__ int g_maskFmt;      // 0=int32, 1=byte, 2=float32
__device__ float g_scale_cp[DF], g_bias_cp[DF], g_scale_pf[DF], g_bias_pf[DF];

// ---------------- mask dtype detection ----------------
__global__ void k_detect(const int* __restrict__ m) {
    int t = threadIdx.x;
    int notInt = 0, notFloat = 0;
    for (int k = t; k < 1000; k += 256) {
        unsigned u = (unsigned)m[k];
        if (u > 1u) notInt = 1;
        if (u != 0u && u != 0x3F800000u) notFloat = 1;
    }
    notInt = __syncthreads_or(notInt);
    notFloat = __syncthreads_or(notFloat);
    if (t == 0) {
        int fmt;
        if (!notInt) fmt = 0;          // int32 0/1
        else if (!notFloat) fmt = 2;   // float32 0.0/1.0
        else fmt = 1;                  // raw bytes
        g_maskFmt = fmt;
    }
}

__device__ __forceinline__ bool get_fg(const void* m, int i) {
    int f = g_maskFmt;
    if (f == 0) return ((const int*)m)[i] != 0;
    if (f == 2) return ((const float*)m)[i] != 0.0f;
    return ((const unsigned char*)m)[i] != 0;
}

// ---------------- zero-init ----------------
__global__ void k_zero() {
    int t = blockIdx.x * blockDim.x + threadIdx.x;
    int stride = gridDim.x * blockDim.x;
    float4 z = make_float4(0.f, 0.f, 0.f, 0.f);
    for (int k = t; k < NPTS * DF / 4; k += stride) { g_csum4[k] = z; g_asum4[k] = z; }
    for (int k = t; k < NPTS; k += stride) { g_cnt[k] = 0.f; g_acnt[k] = 0.f; }
    for (int k = t; k < VWORDS; k += stride) g_bitV[k] = 0u;
    for (int k = t; k < AWORDS; k += stride) g_bitA[k] = 0u;
    if (t == 0) { g_K = -1; g_amaskCnt = 0; }
}

// ---------------- fold BN constants ----------------
__global__ void k_prep(const float* __restrict__ b_pf, const float* __restrict__ gm_pf,
                       const float* __restrict__ be_pf, const float* __restrict__ m_pf,
                       const float* __restrict__ v_pf,
                       const float* __restrict__ b_cp, const float* __restrict__ gm_cp,
                       const float* __restrict__ be_cp, const float* __restrict__ m_cp,
                       const float* __restrict__ v_cp) {
    int j = threadIdx.x;
    float s = gm_cp[j] * rsqrtf(v_cp[j] + 1e-5f);
    g_scale_cp[j] = s;
    g_bias_cp[j] = (b_cp[j] - m_cp[j]) * s + be_cp[j];
    float s2 = gm_pf[j] * rsqrtf(v_pf[j] + 1e-5f);
    g_scale_pf[j] = s2;
    g_bias_pf[j] = (b_pf[j] - m_pf[j]) * s2 + be_pf[j];
}

// ---------------- voxelize + mark bitmaps ----------------
__global__ void k_mark(const float* __restrict__ pc, const int* __restrict__ bidx) {
    int i = blockIdx.x * 256 + threadIdx.x;
    if (i >= NPTS) return;
    float x = pc[3 * i + 0], y = pc[3 * i + 1], z = pc[3 * i + 2];
    int xi = (int)floorf(__fdiv_rn(x - (-50.0f), 0.4f));
    int yi = (int)floorf(__fdiv_rn(y - (-50.0f), 0.4f));
    int zi = (int)floorf(__fdiv_rn(z - (-5.0f), 0.4f));
    xi = min(max(xi, 0), NXC - 1);
    yi = min(max(yi, 0), NYC - 1);
    zi = min(max(zi, 0), NZC - 1);
    int b = bidx[i];
    int local = (xi * NYC + yi) * NZC + zi;
    int vk = b * VXYZ + local;
    int ak = (b >> 1) * VXYZ + local;
    g_vkey[i] = vk;
    g_akey[i] = ak;
    atomicOr(&g_bitV[vk >> 5], 1u << (vk & 31));
    atomicOr(&g_bitA[ak >> 5], 1u << (ak & 31));
}

// ---------------- bitmap popcount scan (3 phases) ----------------
__global__ void k_scan1(int which) {
    const unsigned* bits = which ? g_bitA : g_bitV;
    int* pref = which ? g_prefA : g_prefV;
    int* blks = which ? g_blkA : g_blkV;
    int nwords = which ? AWORDS : VWORDS;
    int w = blockIdx.x * 256 + threadIdx.x;
    int c = (w < nwords) ? __popc(bits[w]) : 0;
    int lane = threadIdx.x & 31, wid = threadIdx.x >> 5;
    int v = c;
#pragma unroll
    for (int o = 1; o < 32; o <<= 1) { int u = __shfl_up_sync(0xffffffffu, v, o); if (lane >= o) v += u; }
    __shared__ int ws[8];
    if (lane == 31) ws[wid] = v;
    __syncthreads();
    if (wid == 0) {
        int x = (lane < 8) ? ws[lane] : 0;
#pragma unroll
        for (int o = 1; o < 8; o <<= 1) { int u = __shfl_up_sync(0xffffffffu, x, o); if (lane >= o) x += u; }
        if (lane < 8) ws[lane] = x;
    }
    __syncthreads();
    int incl = v + (wid > 0 ? ws[wid - 1] : 0);
    if (w < nwords) pref[w] = incl - c;   // exclusive within block
    if (threadIdx.x == 255) blks[blockIdx.x] = incl;
}

__global__ void k_scan2(int which) {
    int nb = which ? ABLOCKS : VBLOCKS;
    int* blk = which ? g_blkA : g_blkV;
    int t = threadIdx.x;
    int i0 = 2 * t, i1 = 2 * t + 1;
    int v0 = (i0 < nb) ? blk[i0] : 0;
    int v1 = (i1 < nb) ? blk[i1] : 0;
    int s = v0 + v1;
    int lane = t & 31, wid = t >> 5;
    int v = s;
#pragma unroll
    for (int o = 1; o < 32; o <<= 1) { int u = __shfl_up_sync(0xffffffffu, v, o); if (lane >= o) v += u; }
    __shared__ int ws[32];
    if (lane == 31) ws[wid] = v;
    __syncthreads();
    if (wid == 0) {
        int x = ws[lane];
#pragma unroll
        for (int o = 1; o < 32; o <<= 1) { int u = __shfl_up_sync(0xffffffffu, x, o); if (lane >= o) x += u; }
        ws[lane] = x;
    }
    __syncthreads();
    int incl = v + (wid > 0 ? ws[wid - 1] : 0);
    int ex = incl - s;
    if (i0 < nb) blk[i0] = ex;
    if (i1 < nb) blk[i1] = ex + v0;
}

__global__ void k_scan3(int which) {
    int nw = which ? AWORDS : VWORDS;
    int* pref = which ? g_prefA : g_prefV;
    const int* blk = which ? g_blkA : g_blkV;
    int w = blockIdx.x * 256 + threadIdx.x;
    if (w < nw) pref[w] += blk[w >> 8];
}

// ---------------- per-point ranks (== unique inverse indices) ----------------
__global__ void k_rank(const void* __restrict__ maskp) {
    int i = blockIdx.x * 256 + threadIdx.x;
    if (i >= NPTS) return;
    int vk = g_vkey[i], ak = g_akey[i];
    int c = g_prefV[vk >> 5] + __popc(g_bitV[vk >> 5] & ((1u << (vk & 31)) - 1u));
    int a = g_prefA[ak >> 5] + __popc(g_bitA[ak >> 5] & ((1u << (ak & 31)) - 1u));
    g_inv[i] = c;
    g_arank[i] = a;
    g_clusterA[c] = a;           // same value from every point of the cluster
    if (get_fg(maskp, i)) atomicMax(&g_K, c);
}

// ---------------- foreground scatter-sum of features ----------------
__global__ void k_featacc(const float* __restrict__ feat, const void* __restrict__ maskp) {
    int t = blockIdx.x * 256 + threadIdx.x;
    int i = t >> 5;
    if (i >= NPTS) return;
    if (!get_fg(maskp, i)) return;
    int c = g_inv[i];
    int j = (t & 31) * 4;
    float4 f = *(const float4*)&feat[(size_t)i * DF + j];
    float* cs = (float*)g_csum4 + (size_t)c * DF + j;
    atomicAdd(cs + 0, f.x);
    atomicAdd(cs + 1, f.y);
    atomicAdd(cs + 2, f.z);
    atomicAdd(cs + 3, f.w);
    if ((t & 31) == 0) atomicAdd(&g_cnt[c], 1.0f);
}

// ---------------- cluster GEMM: cfa = leaky(bn(cmean @ w_cp + b)) ; scatter into asum ----------------
__global__ __launch_bounds__(256) void k_cgemm(const float* __restrict__ w_cp) {
    int Kv = g_K + 1;
    int row0 = blockIdx.x * 64;
    if (row0 >= Kv) return;
    __shared__ __align__(16) float As[16][64];
    __shared__ __align__(16) float Ws[16][128];
    __shared__ float rcs[64];
    __shared__ int aIdx[64];
    int t = threadIdx.x;
    if (t < 64) {
        int c = row0 + t;
        rcs[t] = 1.0f / fmaxf(g_cnt[c], 1.0f);
        aIdx[t] = g_clusterA[c];
    }
    __syncthreads();
    int r = t & 63, kl = (t >> 6) * 4;
    int rg = t >> 4, cg = t & 15;
    float acc[4][8];
#pragma unroll
    for (int q = 0; q < 4; q++)
#pragma unroll
        for (int p = 0; p < 8; p++) acc[q][p] = 0.f;
    const float* csp = (const float*)g_csum4;
    int kw = t >> 5, jw = (t & 31) * 4;
    for (int kt = 0; kt < 128; kt += 16) {
        float4 av = *(const float4*)&csp[(size_t)(row0 + r) * DF + kt + kl];
        float rc = rcs[r];
        As[kl + 0][r] = av.x * rc;
        As[kl + 1][r] = av.y * rc;
        As[kl + 2][r] = av.z * rc;
        As[kl + 3][r] = av.w * rc;
        *(float4*)&Ws[kw][jw]     = *(const float4*)&w_cp[(kt + kw) * DF + jw];
        *(float4*)&Ws[kw + 8][jw] = *(const float4*)&w_cp[(kt + kw + 8) * DF + jw];
        __syncthreads();
#pragma unroll
        for (int k = 0; k < 16; k++) {
            float4 a  = *(const float4*)&As[k][rg * 4];
            float4 b0 = *(const float4*)&Ws[k][cg * 8];
            float4 b1 = *(const float4*)&Ws[k][cg * 8 + 4];
            float aa[4] = {a.x, a.y, a.z, a.w};
            float bb[8] = {b0.x, b0.y, b0.z, b0.w, b1.x, b1.y, b1.z, b1.w};
#pragma unroll
            for (int q = 0; q < 4; q++)
#pragma unroll
                for (int p = 0; p < 8; p++) acc[q][p] += aa[q] * bb[p];
        }
        __syncthreads();
    }
    float sc[8], bi[8];
#pragma unroll
    for (int p = 0; p < 8; p++) { sc[p] = g_scale_cp[cg * 8 + p]; bi[p] = g_bias_cp[cg * 8 + p]; }
    float* cfap = (float*)g_cfa4;
    float* asp  = (float*)g_asum4;
#pragma unroll
    for (int q = 0; q < 4; q++) {
        int c = row0 + rg * 4 + q;
        if (c >= Kv) continue;
        int a = aIdx[rg * 4 + q];
#pragma unroll
        for (int p = 0; p < 8; p++) {
            float v = acc[q][p] * sc[p] + bi[p];
            v = (v >= 0.f) ? v : 0.1f * v;
            cfap[(size_t)c * DF + cg * 8 + p] = v;
            atomicAdd(&asp[(size_t)a * DF + cg * 8 + p], v);
        }
        if (cg == 0) atomicAdd(&g_acnt[a], 1.0f);
    }
}

// ---------------- point GEMM: out = select(amask, leaky(bn(cat @ w_pf + b)), feat) ----------------
__global__ __launch_bounds__(256) void k_pgemm(const float* __restrict__ feat,
                                               const float* __restrict__ w_pf,
                                               float* __restrict__ out) {
    int Kv = g_K + 1;
    int row0 = blockIdx.x * 64;
    __shared__ __align__(16) float As[16][64];
    __shared__ __align__(16) float Ws[16][128];
    __shared__ int ci[64];
    __shared__ int ai[64];
    __shared__ float rca[64];
    __shared__ float d1s[4][64], d2s[4][64];
    int t = threadIdx.x;
    if (t < 64) {
        int i = row0 + t;
        int c = g_inv[i];
        int a = g_arank[i];
        ci[t] = c;
        ai[t] = a;
        rca[t] = 1.0f / fmaxf(g_acnt[a], 1.0f);
    }
    __syncthreads();
    int r = t & 63, kl = (t >> 6) * 4;
    int rg = t >> 4, cg = t & 15;
    float acc[4][8];
#pragma unroll
    for (int q = 0; q < 4; q++)
#pragma unroll
        for (int p = 0; p < 8; p++) acc[q][p] = 0.f;
    float d1 = 0.f, d2 = 0.f;
    const float* cfap = (const float*)g_cfa4;
    const float* asp  = (const float*)g_asum4;
    int myC = ci[r], myA = ai[r];
    float myR = rca[r];
    int i_r = row0 + r;
    int kw = t >> 5, jw = (t & 31) * 4;
    for (int kt = 0; kt < 384; kt += 16) {
        int kk = kt + kl;
        float4 v;
        if (kk < 128) {
            v = *(const float4*)&feat[(size_t)i_r * DF + kk];
        } else if (kk < 256) {
            if (myC < Kv) v = *(const float4*)&cfap[(size_t)myC * DF + (kk - 128)];
            else v = make_float4(0.f, 0.f, 0.f, 0.f);
            float grp = __fadd_rn(__fadd_rn(__fadd_rn(v.x, v.y), v.z), v.w);
            d1 = __fadd_rn(d1, grp);
        } else {
            float4 s = *(const float4*)&asp[(size_t)myA * DF + (kk - 256)];
            v.x = __fmul_rn(s.x, myR);
            v.y = __fmul_rn(s.y, myR);
            v.z = __fmul_rn(s.z, myR);
            v.w = __fmul_rn(s.w, myR);
            float grp = __fadd_rn(__fadd_rn(__fadd_rn(v.x, v.y), v.z), v.w);
            d2 = __fadd_rn(d2, grp);
        }
        As[kl + 0][r] = v.x;
        As[kl + 1][r] = v.y;
        As[kl + 2][r] = v.z;
        As[kl + 3][r] = v.w;
        *(float4*)&Ws[kw][jw]     = *(const float4*)&w_pf[(size_t)(kt + kw) * DF + jw];
        *(float4*)&Ws[kw + 8][jw] = *(const float4*)&w_pf[(size_t)(kt + kw + 8) * DF + jw];
        __syncthreads();
#pragma unroll
        for (int k = 0; k < 16; k++) {
            float4 a  = *(const float4*)&As[k][rg * 4];
            float4 b0 = *(const float4*)&Ws[k][cg * 8];
            float4 b1 = *(const float4*)&Ws[k][cg * 8 + 4];
            float aa[4] = {a.x, a.y, a.z, a.w};
            float bb[8] = {b0.x, b0.y, b0.z, b0.w, b1.x, b1.y, b1.z, b1.w};
#pragma unroll
            for (int q = 0; q < 4; q++)
#pragma unroll
                for (int p = 0; p < 8; p++) acc[q][p] += aa[q] * bb[p];
        }
        __syncthreads();
    }
    d1s[t >> 6][r] = d1;
    d2s[t >> 6][r] = d2;
    __syncthreads();
    float sc[8], bi[8];
#pragma unroll
    for (int p = 0; p < 8; p++) { sc[p] = g_scale_pf[cg * 8 + p]; bi[p] = g_bias_pf[cg * 8 + p]; }
    int cnt = 0;
#pragma unroll
    for (int q = 0; q < 4; q++) {
        int rr = rg * 4 + q;
        float D1 = __fadd_rn(__fadd_rn(__fadd_rn(d1s[0][rr], d1s[1][rr]), d1s[2][rr]), d1s[3][rr]);
        float D2 = __fadd_rn(__fadd_rn(__fadd_rn(d2s[0][rr], d2s[1][rr]), d2s[2][rr]), d2s[3][rr]);
        bool am = __fadd_rn(D1, -D2) > 0.0f;
        int i = row0 + rr;
        if (am) {
#pragma unroll
            for (int p = 0; p < 8; p++) {
                float v = acc[q][p] * sc[p] + bi[p];
                v = (v >= 0.f) ? v : 0.1f * v;
                out[(size_t)i * DF + cg * 8 + p] = v;
            }
            cnt++;
        } else {
            float4 f0 = *(const float4*)&feat[(size_t)i * DF + cg * 8];
            float4 f1 = *(const float4*)&feat[(size_t)i * DF + cg * 8 + 4];
            *(float4*)&out[(size_t)i * DF + cg * 8]     = f0;
            *(float4*)&out[(size_t)i * DF + cg * 8 + 4] = f1;
        }
    }
    if (cg == 0 && cnt) atomicAdd(&g_amaskCnt, cnt);
}

// ---------------- early-return fixup: amask.sum() <= 1 -> out = feat ----------------
__global__ void k_fixup(const float* __restrict__ feat, float* __restrict__ out) {
    if (g_amaskCnt > 1) return;
    int t = blockIdx.x * 256 + threadIdx.x;
    if (t >= NPTS * DF / 4) return;
    ((float4*)out)[t] = ((const float4*)feat)[t];
}

// ---------------- launch ----------------
extern "C" void kernel_launch(void* const* d_in, const int* in_sizes, int n_in,
                              void* d_out, int out_size) {
    const float* feat  = (const float*)d_in[0];
    const float* pc    = (const float*)d_in[1];
    const int*   bidx  = (const int*)d_in[2];
    const void*  maskp = d_in[3];
    // d_in[4] timestamp: net contribution is exactly zero in the reference
    const float* w_pf  = (const float*)d_in[5];
    const float* b_pf  = (const float*)d_in[6];
    const float* gm_pf = (const float*)d_in[7];
    const float* be_pf = (const float*)d_in[8];
    const float* m_pf  = (const float*)d_in[9];
    const float* v_pf  = (const float*)d_in[10];
    const float* w_cp  = (const float*)d_in[11];
    const float* b_cp  = (const float*)d_in[12];
    const float* gm_cp = (const float*)d_in[13];
    const float* be_cp = (const float*)d_in[14];
    const float* m_cp  = (const float*)d_in[15];
    const float* v_cp  = (const float*)d_in[16];
    float* out = (float*)d_out;

    k_detect<<<1, 256>>>((const int*)maskp);
    k_zero<<<2048, 256>>>();
    k_prep<<<1, 128>>>(b_pf, gm_pf, be_pf, m_pf, v_pf, b_cp, gm_cp, be_cp, m_cp, v_cp);
    k_mark<<<(NPTS + 255) / 256, 256>>>(pc, bidx);
    k_scan1<<<VBLOCKS, 256>>>(0);
    k_scan1<<<ABLOCKS, 256>>>(1);
    k_scan2<<<1, 1024>>>(0);
    k_scan2<<<1, 1024>>>(1);
    k_scan3<<<VBLOCKS, 256>>>(0);
    k_scan3<<<ABLOCKS, 256>>>(1);
    k_rank<<<(NPTS + 255) / 256, 256>>>(maskp);
    k_featacc<<<(NPTS * 32 + 255) / 256, 256>>>(feat, maskp);
    k_cgemm<<<GEMM_BLOCKS, 256>>>(w_cp);
    k_pgemm<<<GEMM_BLOCKS, 256>>>(feat, w_pf, out);
    k_fixup<<<(NPTS * DF / 4 + 255) / 256, 256>>>(feat, out);
}